// round 11
// baseline (speedup 1.0000x reference)
#include <cuda_runtime.h>
#include <cuda_bf16.h>
#include <math.h>
#include <stdint.h>

#define HID 128
#define NLV 262144

// ---------------- device buffers (static = allocation-guard safe) ----------------
__device__ __nv_bfloat16 g_Ahi[(size_t)131072 * 256];   // 64 MB
__device__ __nv_bfloat16 g_Alo[(size_t)131072 * 256];   // 64 MB
__device__ __nv_bfloat16 g_Bhi[(size_t)65536 * 256];    // 32 MB
__device__ __nv_bfloat16 g_Blo[(size_t)65536 * 256];    // 32 MB
// K-major split weights (same layout as originals: W[k][n]).
__device__ __nv_bfloat16 g_WLhi[256 * 128], g_WLlo[256 * 128];  // vstack(W_l,W_r)
__device__ __nv_bfloat16 g_WIhi[64 * 128],  g_WIlo[64 * 128];   // W_in
__device__ float g_bsum[128];                                   // b_l + b_r

// ---------------- helpers ----------------
__device__ __forceinline__ uint32_t f2bf2(float a, float b) {
    uint32_t r;
    asm("cvt.rn.bf16x2.f32 %0, %1, %2;" : "=r"(r) : "f"(b), "f"(a));
    return r;
}
__device__ __forceinline__ float bf_lo(uint32_t p) { return __uint_as_float(p << 16); }
__device__ __forceinline__ float bf_hi(uint32_t p) { return __uint_as_float(p & 0xFFFF0000u); }

__device__ __forceinline__ void ldm_x4(uint32_t* r, uint32_t addr) {
    asm volatile("ldmatrix.sync.aligned.m8n8.x4.shared.b16 {%0,%1,%2,%3}, [%4];"
                 : "=r"(r[0]), "=r"(r[1]), "=r"(r[2]), "=r"(r[3]) : "r"(addr));
}
__device__ __forceinline__ void ldm_x4_t(uint32_t* r, uint32_t addr) {
    asm volatile("ldmatrix.sync.aligned.m8n8.x4.trans.shared.b16 {%0,%1,%2,%3}, [%4];"
                 : "=r"(r[0]), "=r"(r[1]), "=r"(r[2]), "=r"(r[3]) : "r"(addr));
}
__device__ __forceinline__ void mma_bf16(float* c, const uint32_t* a, const uint32_t* b) {
    asm volatile("mma.sync.aligned.m16n8k16.row.col.f32.bf16.bf16.f32 "
                 "{%0,%1,%2,%3}, {%4,%5,%6,%7}, {%8,%9}, {%0,%1,%2,%3};"
                 : "+f"(c[0]), "+f"(c[1]), "+f"(c[2]), "+f"(c[3])
                 : "r"(a[0]), "r"(a[1]), "r"(a[2]), "r"(a[3]), "r"(b[0]), "r"(b[1]));
}
__device__ __forceinline__ void cp16(uint32_t dst, const void* src) {
    asm volatile("cp.async.ca.shared.global [%0], [%1], 16;" :: "r"(dst), "l"(src));
}
#define CP_COMMIT() asm volatile("cp.async.commit_group;" ::: "memory")
#define CP_WAIT(N)  asm volatile("cp.async.wait_group %0;" :: "n"(N) : "memory")

// A rows are 128B, W rows are 256B; permute 16B chunks for conflict-free ldmatrix.
#define SWZA(o) ((o) ^ ((((uint32_t)(o)) >> 3) & 0x70))
#define SWZW(o) ((o) ^ (((((uint32_t)(o)) >> 8) & 7) << 4))

// ---------------- smem layout: bias + 2 x 64KB stage buffers ----------------
#define SM_BIAS 0
#define SM_BUF  1024
#define BUF_SZ  65536
#define OFF_AHI 0
#define OFF_ALO 16384
#define OFF_WHI 32768
#define OFF_WLO 49152
#define SMEM_MAIN (1024 + 2 * BUF_SZ)
#define SMEM_LEAF (1024 + BUF_SZ)

// ---------------- prep ----------------
__global__ void prep_kernel(const float* __restrict__ W_in,
                            const float* __restrict__ W_l, const float* __restrict__ b_l,
                            const float* __restrict__ W_r, const float* __restrict__ b_r) {
    int t = blockIdx.x * blockDim.x + threadIdx.x;
    int stride = gridDim.x * blockDim.x;
    for (int idx = t; idx < 256 * 128; idx += stride) {
        float w = (idx < 128 * 128) ? W_l[idx] : W_r[idx - 128 * 128];
        __nv_bfloat16 h = __float2bfloat16(w);
        g_WLhi[idx] = h;
        g_WLlo[idx] = __float2bfloat16(w - __bfloat162float(h));
    }
    for (int idx = t; idx < 64 * 128; idx += stride) {
        float w = W_in[idx];
        __nv_bfloat16 h = __float2bfloat16(w);
        g_WIhi[idx] = h;
        g_WIlo[idx] = __float2bfloat16(w - __bfloat162float(h));
    }
    if (t < 128) g_bsum[t] = b_l[t] + b_r[t];
}

// ---------------- main level kernel (unchanged from R6 — proven) ----------------
template <int K, bool LEAF>
__global__ void __launch_bounds__(512, 1)
rnn_level(const float* __restrict__ leafX,
          const __nv_bfloat16* __restrict__ Ahi, const __nv_bfloat16* __restrict__ Alo,
          const __nv_bfloat16* __restrict__ Whi, const __nv_bfloat16* __restrict__ Wlo,
          const float* __restrict__ bias,
          __nv_bfloat16* __restrict__ nHi, __nv_bfloat16* __restrict__ nLo) {
    extern __shared__ char smem[];
    const uint32_t sb = (uint32_t)__cvta_generic_to_shared(smem);
    const int tid = threadIdx.x, l = tid & 31, wid = tid >> 5;
    const int wm = wid & 7, wn = wid >> 3;          // warp grid 8 (m) x 2 (n)
    const int m0 = blockIdx.x * 128;
    constexpr int NST = K / 64;

    if (tid < 128) ((float*)(smem + SM_BIAS))[tid] = bias[tid];

    float acc[8][4];
    #pragma unroll
    for (int nt = 0; nt < 8; nt++)
        #pragma unroll
        for (int q = 0; q < 4; q++) acc[nt][q] = 0.f;

    auto load_stage = [&](int st, int buf) {
        const uint32_t bb = sb + SM_BUF + buf * BUF_SZ;
        #pragma unroll 2
        for (int i = tid; i < 1024; i += 512) {
            int r = i >> 3, kg = i & 7;
            uint32_t off = SWZA((uint32_t)(r * 128 + kg * 16));
            size_t gi = (size_t)(m0 + r) * K + st * 64 + kg * 8;
            cp16(bb + OFF_AHI + off, Ahi + gi);
            cp16(bb + OFF_ALO + off, Alo + gi);
        }
        #pragma unroll 2
        for (int i = tid; i < 1024; i += 512) {
            int kr = i >> 4, ch = i & 15;
            uint32_t off = SWZW((uint32_t)(kr * 256 + ch * 16));
            size_t gi = (size_t)(st * 64 + kr) * 128 + ch * 8;
            cp16(bb + OFF_WHI + off, Whi + gi);
            cp16(bb + OFF_WLO + off, Wlo + gi);
        }
    };

    auto compute_stage = [&](int buf) {
        const uint32_t bb = sb + SM_BUF + buf * BUF_SZ;
        #pragma unroll
        for (int ks = 0; ks < 4; ks++) {
            uint32_t ah[4], al[4], bh[8][2], bl[8][2];
            {
                int row = wm * 16 + (l & 15);
                uint32_t aoff = SWZA((uint32_t)(row * 128 + ks * 32 + (l >> 4) * 16));
                ldm_x4(ah, bb + OFF_AHI + aoff);
                ldm_x4(al, bb + OFF_ALO + aoff);
            }
            #pragma unroll
            for (int ntp = 0; ntp < 4; ntp++) {
                int krow = ks * 16 + (l & 15);
                int nb   = (wn * 64 + ntp * 16 + (l >> 4) * 8) * 2;
                uint32_t woff = SWZW((uint32_t)(krow * 256 + nb));
                uint32_t t4[4];
                ldm_x4_t(t4, bb + OFF_WHI + woff);
                bh[ntp * 2][0] = t4[0]; bh[ntp * 2][1] = t4[1];
                bh[ntp * 2 + 1][0] = t4[2]; bh[ntp * 2 + 1][1] = t4[3];
                ldm_x4_t(t4, bb + OFF_WLO + woff);
                bl[ntp * 2][0] = t4[0]; bl[ntp * 2][1] = t4[1];
                bl[ntp * 2 + 1][0] = t4[2]; bl[ntp * 2 + 1][1] = t4[3];
            }
            #pragma unroll
            for (int nt = 0; nt < 8; nt++) mma_bf16(acc[nt], ah, bh[nt]);
            #pragma unroll
            for (int nt = 0; nt < 8; nt++) mma_bf16(acc[nt], ah, bl[nt]);
            #pragma unroll
            for (int nt = 0; nt < 8; nt++) mma_bf16(acc[nt], al, bh[nt]);
        }
    };

    if (LEAF) {
        const uint32_t bb = sb + SM_BUF;
        #pragma unroll 2
        for (int i = tid; i < 1024; i += 512) {
            int kr = i >> 4, ch = i & 15;
            uint32_t off = SWZW((uint32_t)(kr * 256 + ch * 16));
            size_t gi = (size_t)kr * 128 + ch * 8;
            cp16(bb + OFF_WHI + off, Whi + gi);
            cp16(bb + OFF_WLO + off, Wlo + gi);
        }
        CP_COMMIT();
        #pragma unroll 2
        for (int i = tid; i < 1024; i += 512) {
            int r = i >> 3, kg = i & 7;
            const float* src = leafX + (size_t)(m0 + r) * 64 + kg * 8;
            float4 f0 = *(const float4*)src;
            float4 f1 = *(const float4*)(src + 4);
            float xs[8] = {f0.x, f0.y, f0.z, f0.w, f1.x, f1.y, f1.z, f1.w};
            uint32_t hp[4], lp[4];
            #pragma unroll
            for (int j = 0; j < 4; j++) {
                hp[j] = f2bf2(xs[2 * j], xs[2 * j + 1]);
                lp[j] = f2bf2(xs[2 * j] - bf_lo(hp[j]), xs[2 * j + 1] - bf_hi(hp[j]));
            }
            uint32_t off = SWZA((uint32_t)(r * 128 + kg * 16));
            *(uint4*)(smem + SM_BUF + OFF_AHI + off) = make_uint4(hp[0], hp[1], hp[2], hp[3]);
            *(uint4*)(smem + SM_BUF + OFF_ALO + off) = make_uint4(lp[0], lp[1], lp[2], lp[3]);
        }
        CP_WAIT(0);
        __syncthreads();
        compute_stage(0);
    } else {
        load_stage(0, 0);
        CP_COMMIT();
        for (int st = 0; st < NST; st++) {
            if (st + 1 < NST) {
                load_stage(st + 1, (st + 1) & 1);
                CP_COMMIT();
                CP_WAIT(1);
            } else {
                CP_WAIT(0);
            }
            __syncthreads();
            compute_stage(st & 1);
            __syncthreads();
        }
    }

    const float* sBias = (const float*)(smem + SM_BIAS);
    #pragma unroll
    for (int nt = 0; nt < 8; nt++) {
        int c = wn * 64 + nt * 8 + (l & 3) * 2;
        #pragma unroll
        for (int half = 0; half < 2; half++) {
            int gm = m0 + wm * 16 + (l >> 2) + half * 8;
            float x0 = acc[nt][half * 2]     + sBias[c];
            float x1 = acc[nt][half * 2 + 1] + sBias[c + 1];
            float t0 = tanhf(x0), t1 = tanhf(x1);
            uint32_t hp = f2bf2(t0, t1);
            uint32_t lp = f2bf2(t0 - bf_lo(hp), t1 - bf_hi(hp));
            size_t base = (size_t)(gm >> 1) * 256 + (size_t)((gm & 1) * 128 + c);
            *(uint32_t*)(nHi + base) = hp;
            *(uint32_t*)(nLo + base) = lp;
        }
    }
}

// ---------------- tail kernel: levels Mout=128..1, single CTA, fp32, W in smem ----
// Thread = (row r = tid>>2, col-group cg = tid&3 -> 32 cols). W = vstack(W_l,W_r)
// fp32 in smem (128 KB). A read from global bf16 hi/lo pairs (L2-hot, tiny).
// Intermediates ping-pong through global scratch pair buffers.
#define SMEM_TAIL (256 * 128 * 4 + 512)
__global__ void __launch_bounds__(512, 1)
rnn_tail(const __nv_bfloat16* __restrict__ Ahi, const __nv_bfloat16* __restrict__ Alo,
         __nv_bfloat16* __restrict__ scrH, __nv_bfloat16* __restrict__ scrL,
         const float* __restrict__ W_l, const float* __restrict__ W_r,
         const float* __restrict__ bsum, float* __restrict__ out) {
    extern __shared__ float fs[];
    float* sW = fs;                  // [256][128]
    float* sB = fs + 256 * 128;
    const int tid = threadIdx.x;

    for (int i = tid; i < 128 * 128; i += 512) {
        sW[i] = W_l[i];
        sW[128 * 128 + i] = W_r[i];
    }
    if (tid < 128) sB[tid] = bsum[tid];
    __syncthreads();

    const int r  = tid >> 2;
    const int cg = tid & 3;
    const float4* sB4 = (const float4*)(sB + cg * 32);

    const __nv_bfloat16* cH = Ahi;
    const __nv_bfloat16* cL = Alo;
    int ping = 0;
    for (int Mout = 128; Mout >= 1; Mout >>= 1) {
        __nv_bfloat16* nH = scrH + ping * 32768;
        __nv_bfloat16* nL = scrL + ping * 32768;
        if (r < Mout) {
            float4 acc[8];
            #pragma unroll
            for (int c4 = 0; c4 < 8; c4++) acc[c4] = sB4[c4];

            const uint4* hR = (const uint4*)(cH + (size_t)r * 256);
            const uint4* lR = (const uint4*)(cL + (size_t)r * 256);
            #pragma unroll 4
            for (int k8 = 0; k8 < 32; k8++) {           // 8 k per iteration
                uint4 h4 = hR[k8];
                uint4 l4 = lR[k8];
                float a[8];
                a[0] = bf_lo(h4.x) + bf_lo(l4.x);  a[1] = bf_hi(h4.x) + bf_hi(l4.x);
                a[2] = bf_lo(h4.y) + bf_lo(l4.y);  a[3] = bf_hi(h4.y) + bf_hi(l4.y);
                a[4] = bf_lo(h4.z) + bf_lo(l4.z);  a[5] = bf_hi(h4.z) + bf_hi(l4.z);
                a[6] = bf_lo(h4.w) + bf_lo(l4.w);  a[7] = bf_hi(h4.w) + bf_hi(l4.w);
                #pragma unroll
                for (int j = 0; j < 8; j++) {
                    const float4* wr = (const float4*)(sW + (k8 * 8 + j) * 128 + cg * 32);
                    #pragma unroll
                    for (int c4 = 0; c4 < 8; c4++) {
                        float4 w = wr[c4];
                        acc[c4].x = fmaf(a[j], w.x, acc[c4].x);
                        acc[c4].y = fmaf(a[j], w.y, acc[c4].y);
                        acc[c4].z = fmaf(a[j], w.z, acc[c4].z);
                        acc[c4].w = fmaf(a[j], w.w, acc[c4].w);
                    }
                }
            }

            #pragma unroll
            for (int c4 = 0; c4 < 8; c4++) {
                int c = cg * 32 + c4 * 4;
                float t0 = tanhf(acc[c4].x), t1 = tanhf(acc[c4].y);
                float t2 = tanhf(acc[c4].z), t3 = tanhf(acc[c4].w);
                if (Mout == 1) {
                    out[c] = t0; out[c + 1] = t1; out[c + 2] = t2; out[c + 3] = t3;
                } else {
                    uint32_t hp0 = f2bf2(t0, t1), hp1 = f2bf2(t2, t3);
                    uint32_t lp0 = f2bf2(t0 - bf_lo(hp0), t1 - bf_hi(hp0));
                    uint32_t lp1 = f2bf2(t2 - bf_lo(hp1), t3 - bf_hi(hp1));
                    size_t base = (size_t)(r >> 1) * 256 + (size_t)((r & 1) * 128 + c);
                    *(uint2*)(nH + base) = make_uint2(hp0, hp1);
                    *(uint2*)(nL + base) = make_uint2(lp0, lp1);
                }
            }
        }
        __syncthreads();   // orders this level's global writes before next level's reads
        cH = nH; cL = nL; ping ^= 1;
    }
}

// ---------------- host ----------------
extern "C" void kernel_launch(void* const* d_in, const int* in_sizes, int n_in,
                              void* d_out, int out_size) {
    const float* leaf_x = (const float*)d_in[0];
    const float* W_in   = (const float*)d_in[1];
    const float* b_in   = (const float*)d_in[2];
    const float* W_l    = (const float*)d_in[3];
    const float* b_l    = (const float*)d_in[4];
    const float* W_r    = (const float*)d_in[5];
    const float* b_r    = (const float*)d_in[6];

    void *pAh, *pAl, *pBh, *pBl, *pWLh, *pWLl, *pWIh, *pWIl, *pbs;
    cudaGetSymbolAddress(&pAh, g_Ahi);    cudaGetSymbolAddress(&pAl, g_Alo);
    cudaGetSymbolAddress(&pBh, g_Bhi);    cudaGetSymbolAddress(&pBl, g_Blo);
    cudaGetSymbolAddress(&pWLh, g_WLhi);  cudaGetSymbolAddress(&pWLl, g_WLlo);
    cudaGetSymbolAddress(&pWIh, g_WIhi);  cudaGetSymbolAddress(&pWIl, g_WIlo);
    cudaGetSymbolAddress(&pbs, g_bsum);
    __nv_bfloat16 *Ah = (__nv_bfloat16*)pAh, *Al = (__nv_bfloat16*)pAl;
    __nv_bfloat16 *Bh = (__nv_bfloat16*)pBh, *Bl = (__nv_bfloat16*)pBl;
    __nv_bfloat16 *WLh = (__nv_bfloat16*)pWLh, *WLl = (__nv_bfloat16*)pWLl;
    __nv_bfloat16 *WIh = (__nv_bfloat16*)pWIh, *WIl = (__nv_bfloat16*)pWIl;
    float* bsum = (float*)pbs;

    cudaFuncSetAttribute(rnn_level<64, true>,   cudaFuncAttributeMaxDynamicSharedMemorySize, SMEM_LEAF);
    cudaFuncSetAttribute(rnn_level<256, false>, cudaFuncAttributeMaxDynamicSharedMemorySize, SMEM_MAIN);
    cudaFuncSetAttribute(rnn_tail, cudaFuncAttributeMaxDynamicSharedMemorySize, SMEM_TAIL);

    prep_kernel<<<64, 256>>>(W_in, W_l, b_l, W_r, b_r);

    // Leaf: H0[262144,128] -> pairs into (Ah, Al).
    rnn_level<64, true><<<NLV / 128, 512, SMEM_LEAF>>>(
        leaf_x, nullptr, nullptr, WIh, WIl, b_in, Ah, Al);

    // Internal mma levels while Mout >= 256 (10 launches), ping-pong pairs.
    __nv_bfloat16 *curH = Ah, *curL = Al;
    for (int M = NLV / 2; M >= 256; M >>= 1) {
        __nv_bfloat16* nxtH = (curH == Ah) ? Bh : Ah;
        __nv_bfloat16* nxtL = (curL == Al) ? Bl : Al;
        rnn_level<256, false><<<M / 128, 512, SMEM_MAIN>>>(
            nullptr, curH, curL, WLh, WLl, bsum, nxtH, nxtL);
        curH = nxtH; curL = nxtL;
    }

    // Tail: levels Mout=128..1 in one CTA (W fp32 in smem), writes d_out[128].
    __nv_bfloat16* sH = (curH == Ah) ? Bh : Ah;   // scratch = buffer not holding input
    __nv_bfloat16* sL = (curL == Al) ? Bl : Al;
    rnn_tail<<<1, 512, SMEM_TAIL>>>(curH, curL, sH, sL, W_l, W_r, bsum, (float*)d_out);
}

// round 12
// speedup vs baseline: 3.1076x; 3.1076x over previous
#include <cuda_runtime.h>
#include <cuda_bf16.h>
#include <math.h>
#include <stdint.h>

#define HID 128
#define NLV 262144
#define NCTA 128

// ---------------- device buffers (static = allocation-guard safe) ----------------
__device__ __nv_bfloat16 g_Ahi[(size_t)131072 * 256];   // 64 MB
__device__ __nv_bfloat16 g_Alo[(size_t)131072 * 256];   // 64 MB
__device__ __nv_bfloat16 g_Bhi[(size_t)65536 * 256];    // 32 MB
__device__ __nv_bfloat16 g_Blo[(size_t)65536 * 256];    // 32 MB
__device__ __nv_bfloat16 g_WLhi[256 * 128], g_WLlo[256 * 128];  // vstack(W_l,W_r)
__device__ __nv_bfloat16 g_WIhi[64 * 128],  g_WIlo[64 * 128];   // W_in
__device__ float g_bsum[128];                                   // b_l + b_r
__device__ float g_bin[128];                                    // b_in copy
__device__ unsigned g_bar_count;
__device__ unsigned g_bar_sense;

// ---------------- helpers ----------------
__device__ __forceinline__ uint32_t f2bf2(float a, float b) {
    uint32_t r;
    asm("cvt.rn.bf16x2.f32 %0, %1, %2;" : "=r"(r) : "f"(b), "f"(a));
    return r;
}
__device__ __forceinline__ float bf_lo(uint32_t p) { return __uint_as_float(p << 16); }
__device__ __forceinline__ float bf_hi(uint32_t p) { return __uint_as_float(p & 0xFFFF0000u); }

__device__ __forceinline__ void ldm_x4(uint32_t* r, uint32_t addr) {
    asm volatile("ldmatrix.sync.aligned.m8n8.x4.shared.b16 {%0,%1,%2,%3}, [%4];"
                 : "=r"(r[0]), "=r"(r[1]), "=r"(r[2]), "=r"(r[3]) : "r"(addr));
}
__device__ __forceinline__ void ldm_x4_t(uint32_t* r, uint32_t addr) {
    asm volatile("ldmatrix.sync.aligned.m8n8.x4.trans.shared.b16 {%0,%1,%2,%3}, [%4];"
                 : "=r"(r[0]), "=r"(r[1]), "=r"(r[2]), "=r"(r[3]) : "r"(addr));
}
__device__ __forceinline__ void mma_bf16(float* c, const uint32_t* a, const uint32_t* b) {
    asm volatile("mma.sync.aligned.m16n8k16.row.col.f32.bf16.bf16.f32 "
                 "{%0,%1,%2,%3}, {%4,%5,%6,%7}, {%8,%9}, {%0,%1,%2,%3};"
                 : "+f"(c[0]), "+f"(c[1]), "+f"(c[2]), "+f"(c[3])
                 : "r"(a[0]), "r"(a[1]), "r"(a[2]), "r"(a[3]), "r"(b[0]), "r"(b[1]));
}
__device__ __forceinline__ void cp16(uint32_t dst, const void* src) {
    asm volatile("cp.async.ca.shared.global [%0], [%1], 16;" :: "r"(dst), "l"(src));
}
#define CP_COMMIT() asm volatile("cp.async.commit_group;" ::: "memory")
#define CP_WAIT(N)  asm volatile("cp.async.wait_group %0;" :: "n"(N) : "memory")

#define SWZA(o) ((o) ^ ((((uint32_t)(o)) >> 3) & 0x70))
#define SWZW(o) ((o) ^ (((((uint32_t)(o)) >> 8) & 7) << 4))

// ---------------- smem layout ----------------
// [0,512)      bias (fp32 x 128)
// [1024, +64K) W hi  (256 rows x 256B, SWZW)
// [.. , +64K)  W lo
// [132096, +2*32K) A double buffer: per buf AHI(16K) + ALO(16K)
#define SM_BIAS 0
#define SM_W    1024
#define SM_WLO_OFF 65536
#define SM_A    (1024 + 131072)
#define ABUF_SZ 32768
#define SMEM_ALL (SM_A + 2 * ABUF_SZ)   // 197632 B

// ---------------- grid barrier (all CTAs resident: grid=128 <= #SMs, 1 CTA/SM) ----
__device__ __forceinline__ void grid_barrier(unsigned b) {
    __syncthreads();
    if (threadIdx.x == 0) {
        __threadfence();
        unsigned arrived = atomicAdd(&g_bar_count, 1u);
        if (arrived == NCTA - 1) {
            g_bar_count = 0;
            asm volatile("st.release.gpu.global.u32 [%0], %1;"
                         :: "l"(&g_bar_sense), "r"(b) : "memory");
        } else {
            unsigned s;
            do {
                asm volatile("ld.acquire.gpu.global.u32 %0, [%1];"
                             : "=r"(s) : "l"(&g_bar_sense) : "memory");
                if (s < b) __nanosleep(64);
            } while (s < b);
        }
    }
    __syncthreads();
}

// ---------------- prep: split weights, bias sums, reset barrier ----------------
__global__ void prep_kernel(const float* __restrict__ W_in, const float* __restrict__ b_in,
                            const float* __restrict__ W_l, const float* __restrict__ b_l,
                            const float* __restrict__ W_r, const float* __restrict__ b_r) {
    int t = blockIdx.x * blockDim.x + threadIdx.x;
    int stride = gridDim.x * blockDim.x;
    if (t == 0) { g_bar_count = 0; g_bar_sense = 0; }
    for (int idx = t; idx < 256 * 128; idx += stride) {
        float w = (idx < 128 * 128) ? W_l[idx] : W_r[idx - 128 * 128];
        __nv_bfloat16 h = __float2bfloat16(w);
        g_WLhi[idx] = h;
        g_WLlo[idx] = __float2bfloat16(w - __bfloat162float(h));
    }
    for (int idx = t; idx < 64 * 128; idx += stride) {
        float w = W_in[idx];
        __nv_bfloat16 h = __float2bfloat16(w);
        g_WIhi[idx] = h;
        g_WIlo[idx] = __float2bfloat16(w - __bfloat162float(h));
    }
    if (t < 128) { g_bsum[t] = b_l[t] + b_r[t]; g_bin[t] = b_in[t]; }
}

// ---------------- persistent all-levels kernel ----------------
__global__ void __launch_bounds__(512, 1)
rnn_all(const float* __restrict__ leafX, float* __restrict__ out) {
    extern __shared__ char smem[];
    const uint32_t sb = (uint32_t)__cvta_generic_to_shared(smem);
    const int tid = threadIdx.x, l = tid & 31, wid = tid >> 5;
    const int wm = wid & 7, wn = wid >> 3;          // warp grid 8 (m) x 2 (n)
    const int cta = blockIdx.x;

    // ---- load W (R rows) hi/lo into resident smem region ----
    auto load_w = [&](const __nv_bfloat16* Whi, const __nv_bfloat16* Wlo, int R) {
        for (int i = tid; i < R * 16; i += 512) {
            int kr = i >> 4, ch = i & 15;
            uint32_t off = SWZW((uint32_t)(kr * 256 + ch * 16));
            cp16(sb + SM_W + off, Whi + (size_t)kr * 128 + ch * 8);
            cp16(sb + SM_W + SM_WLO_OFF + off, Wlo + (size_t)kr * 128 + ch * 8);
        }
        CP_COMMIT();
        CP_WAIT(0);
        __syncthreads();
    };

    // ---- compute one 64-wide K stage (A in buf, W at k offset st*64) ----
    auto compute_stage = [&](float (*acc)[4], int buf, int st) {
        const uint32_t ab = sb + SM_A + buf * ABUF_SZ;
        #pragma unroll
        for (int ks = 0; ks < 4; ks++) {
            uint32_t ah[4], al[4], bh[8][2], bl[8][2];
            {
                int row = wm * 16 + (l & 15);
                uint32_t aoff = SWZA((uint32_t)(row * 128 + ks * 32 + (l >> 4) * 16));
                ldm_x4(ah, ab + aoff);
                ldm_x4(al, ab + 16384 + aoff);
            }
            #pragma unroll
            for (int ntp = 0; ntp < 4; ntp++) {
                int krow = st * 64 + ks * 16 + (l & 15);
                int nb   = (wn * 64 + ntp * 16 + (l >> 4) * 8) * 2;
                uint32_t woff = SWZW((uint32_t)(krow * 256 + nb));
                uint32_t t4[4];
                ldm_x4_t(t4, sb + SM_W + woff);
                bh[ntp * 2][0] = t4[0]; bh[ntp * 2][1] = t4[1];
                bh[ntp * 2 + 1][0] = t4[2]; bh[ntp * 2 + 1][1] = t4[3];
                ldm_x4_t(t4, sb + SM_W + SM_WLO_OFF + woff);
                bl[ntp * 2][0] = t4[0]; bl[ntp * 2][1] = t4[1];
                bl[ntp * 2 + 1][0] = t4[2]; bl[ntp * 2 + 1][1] = t4[3];
            }
            #pragma unroll
            for (int nt = 0; nt < 8; nt++) mma_bf16(acc[nt], ah, bh[nt]);
            #pragma unroll
            for (int nt = 0; nt < 8; nt++) mma_bf16(acc[nt], ah, bl[nt]);
            #pragma unroll
            for (int nt = 0; nt < 8; nt++) mma_bf16(acc[nt], al, bh[nt]);
        }
    };

    // ---- epilogue: bias + tanh + hi/lo split paired-row store ----
    auto epilogue = [&](float (*acc)[4], int m0,
                        __nv_bfloat16* nHi, __nv_bfloat16* nLo, bool write_out) {
        const float* sBias = (const float*)(smem + SM_BIAS);
        #pragma unroll
        for (int nt = 0; nt < 8; nt++) {
            int c = wn * 64 + nt * 8 + (l & 3) * 2;
            #pragma unroll
            for (int half = 0; half < 2; half++) {
                int gm = m0 + wm * 16 + (l >> 2) + half * 8;
                float x0 = acc[nt][half * 2]     + sBias[c];
                float x1 = acc[nt][half * 2 + 1] + sBias[c + 1];
                float t0 = tanhf(x0), t1 = tanhf(x1);
                uint32_t hp = f2bf2(t0, t1);
                uint32_t lp = f2bf2(t0 - bf_lo(hp), t1 - bf_hi(hp));
                size_t base = (size_t)(gm >> 1) * 256 + (size_t)((gm & 1) * 128 + c);
                *(uint32_t*)(nHi + base) = hp;
                *(uint32_t*)(nLo + base) = lp;
                if (write_out && gm == 0) { out[c] = t0; out[c + 1] = t1; }
            }
        }
    };

    // ============ PHASE 1: leaf  H0 = tanh(leafX @ W_in + b_in) ============
    load_w(g_WIhi, g_WIlo, 64);
    if (tid < 128) ((float*)(smem + SM_BIAS))[tid] = g_bin[tid];
    __syncthreads();

    for (int t = cta; t < NLV / 128; t += NCTA) {
        const int m0 = t * 128;
        // convert fp32 leaf rows -> bf16 hi/lo into A buf 0
        for (int i = tid; i < 1024; i += 512) {
            int r = i >> 3, kg = i & 7;
            const float* src = leafX + (size_t)(m0 + r) * 64 + kg * 8;
            float4 f0 = *(const float4*)src;
            float4 f1 = *(const float4*)(src + 4);
            float xs[8] = {f0.x, f0.y, f0.z, f0.w, f1.x, f1.y, f1.z, f1.w};
            uint32_t hp[4], lp[4];
            #pragma unroll
            for (int j = 0; j < 4; j++) {
                hp[j] = f2bf2(xs[2 * j], xs[2 * j + 1]);
                lp[j] = f2bf2(xs[2 * j] - bf_lo(hp[j]), xs[2 * j + 1] - bf_hi(hp[j]));
            }
            uint32_t off = SWZA((uint32_t)(r * 128 + kg * 16));
            *(uint4*)(smem + SM_A + off)         = make_uint4(hp[0], hp[1], hp[2], hp[3]);
            *(uint4*)(smem + SM_A + 16384 + off) = make_uint4(lp[0], lp[1], lp[2], lp[3]);
        }
        __syncthreads();
        float acc[8][4];
        #pragma unroll
        for (int nt = 0; nt < 8; nt++)
            #pragma unroll
            for (int q = 0; q < 4; q++) acc[nt][q] = 0.f;
        compute_stage(acc, 0, 0);
        __syncthreads();
        epilogue(acc, m0, g_Ahi, g_Alo, false);
    }

    unsigned bar = 1;
    grid_barrier(bar);

    // ============ PHASE 2: 18 internal levels ============
    load_w(g_WLhi, g_WLlo, 256);
    if (tid < 128) ((float*)(smem + SM_BIAS))[tid] = g_bsum[tid];
    __syncthreads();

    const __nv_bfloat16* cH = g_Ahi;
    const __nv_bfloat16* cL = g_Alo;
    int Mo = NLV / 2;
    for (int lvl = 0; lvl < 18; lvl++) {
        __nv_bfloat16* nH = (cH == g_Ahi) ? g_Bhi : g_Ahi;
        __nv_bfloat16* nL = (cL == g_Alo) ? g_Blo : g_Alo;
        const int tiles = (Mo + 127) >> 7;
        const bool last = (Mo == 1);

        auto load_a = [&](int m0, int st, int buf) {
            const uint32_t ab = sb + SM_A + buf * ABUF_SZ;
            #pragma unroll 2
            for (int i = tid; i < 1024; i += 512) {
                int r = i >> 3, kg = i & 7;
                uint32_t off = SWZA((uint32_t)(r * 128 + kg * 16));
                size_t gi = (size_t)(m0 + r) * 256 + st * 64 + kg * 8;
                cp16(ab + off, cH + gi);
                cp16(ab + 16384 + off, cL + gi);
            }
        };

        for (int t = cta; t < tiles; t += NCTA) {
            const int m0 = t * 128;
            float acc[8][4];
            #pragma unroll
            for (int nt = 0; nt < 8; nt++)
                #pragma unroll
                for (int q = 0; q < 4; q++) acc[nt][q] = 0.f;

            load_a(m0, 0, 0);
            CP_COMMIT();
            #pragma unroll
            for (int st = 0; st < 4; st++) {
                if (st < 3) {
                    load_a(m0, st + 1, (st + 1) & 1);
                    CP_COMMIT();
                    CP_WAIT(1);
                } else {
                    CP_WAIT(0);
                }
                __syncthreads();
                compute_stage(acc, st & 1, st);
                __syncthreads();
            }
            epilogue(acc, m0, nH, nL, last);
        }

        if (lvl < 17) grid_barrier(++bar);
        cH = nH; cL = nL; Mo >>= 1;
    }
}

// ---------------- host ----------------
extern "C" void kernel_launch(void* const* d_in, const int* in_sizes, int n_in,
                              void* d_out, int out_size) {
    const float* leaf_x = (const float*)d_in[0];
    const float* W_in   = (const float*)d_in[1];
    const float* b_in   = (const float*)d_in[2];
    const float* W_l    = (const float*)d_in[3];
    const float* b_l    = (const float*)d_in[4];
    const float* W_r    = (const float*)d_in[5];
    const float* b_r    = (const float*)d_in[6];

    cudaFuncSetAttribute(rnn_all, cudaFuncAttributeMaxDynamicSharedMemorySize, SMEM_ALL);

    prep_kernel<<<64, 256>>>(W_in, b_in, W_l, b_l, W_r, b_r);
    rnn_all<<<NCTA, 512, SMEM_ALL>>>(leaf_x, (float*)d_out);
}

// round 14
// speedup vs baseline: 4.3168x; 1.3891x over previous
#include <cuda_runtime.h>
#include <cuda_bf16.h>
#include <math.h>
#include <stdint.h>

#define HID 128
#define NLV 262144
#define NCTA 128

// ---------------- device buffers (static = allocation-guard safe) ----------------
__device__ __nv_bfloat16 g_Ahi[(size_t)65536 * 256];    // 32 MB (P ping)
__device__ __nv_bfloat16 g_Alo[(size_t)65536 * 256];    // 32 MB
__device__ __nv_bfloat16 g_Bhi[(size_t)16384 * 256];    //  8 MB (P pong)
__device__ __nv_bfloat16 g_Blo[(size_t)16384 * 256];    //  8 MB
__device__ __nv_bfloat16 g_WLhi[256 * 128], g_WLlo[256 * 128];  // vstack(W_l,W_r)
__device__ __nv_bfloat16 g_WIhi[64 * 128],  g_WIlo[64 * 128];   // W_in
__device__ float g_bsum[128];
__device__ float g_bin[128];
__device__ unsigned g_bar_count;
__device__ unsigned g_bar_sense;

// ---------------- helpers ----------------
__device__ __forceinline__ uint32_t f2bf2(float a, float b) {
    uint32_t r;
    asm("cvt.rn.bf16x2.f32 %0, %1, %2;" : "=r"(r) : "f"(b), "f"(a));
    return r;
}
__device__ __forceinline__ float bf_lo(uint32_t p) { return __uint_as_float(p << 16); }
__device__ __forceinline__ float bf_hi(uint32_t p) { return __uint_as_float(p & 0xFFFF0000u); }

__device__ __forceinline__ void ldm_x4(uint32_t* r, uint32_t addr) {
    asm volatile("ldmatrix.sync.aligned.m8n8.x4.shared.b16 {%0,%1,%2,%3}, [%4];"
                 : "=r"(r[0]), "=r"(r[1]), "=r"(r[2]), "=r"(r[3]) : "r"(addr));
}
__device__ __forceinline__ void ldm_x4_t(uint32_t* r, uint32_t addr) {
    asm volatile("ldmatrix.sync.aligned.m8n8.x4.trans.shared.b16 {%0,%1,%2,%3}, [%4];"
                 : "=r"(r[0]), "=r"(r[1]), "=r"(r[2]), "=r"(r[3]) : "r"(addr));
}
__device__ __forceinline__ void mma_bf16(float* c, const uint32_t* a, const uint32_t* b) {
    asm volatile("mma.sync.aligned.m16n8k16.row.col.f32.bf16.bf16.f32 "
                 "{%0,%1,%2,%3}, {%4,%5,%6,%7}, {%8,%9}, {%0,%1,%2,%3};"
                 : "+f"(c[0]), "+f"(c[1]), "+f"(c[2]), "+f"(c[3])
                 : "r"(a[0]), "r"(a[1]), "r"(a[2]), "r"(a[3]), "r"(b[0]), "r"(b[1]));
}
__device__ __forceinline__ void cp16(uint32_t dst, const void* src) {
    asm volatile("cp.async.ca.shared.global [%0], [%1], 16;" :: "r"(dst), "l"(src));
}
#define CP_COMMIT() asm volatile("cp.async.commit_group;" ::: "memory")
#define CP_WAIT(N)  asm volatile("cp.async.wait_group %0;" :: "n"(N) : "memory")

// SWZA: A tiles, 128B rows. SWZW: W, 256B rows. SWZB: smem P, 512B rows.
#define SWZA(o) ((o) ^ ((((uint32_t)(o)) >> 3) & 0x70))
#define SWZW(o) ((o) ^ (((((uint32_t)(o)) >> 8) & 7) << 4))
#define SWZB(o) ((o) ^ (((((uint32_t)(o)) >> 9) & 7) << 4))

// ---------------- smem layout ----------------
// [0,512)    b_in   [512,1024) bsum
// [1024, +64K)  W hi (256 rows x 256B SWZW)   [+64K, +128K) W lo
// S0/S1/S2: three 32KB slots (A stage slots; S1/S2 recycled as smem-P hi/lo)
#define SM_BIN  0
#define SM_BSUM 512
#define SM_W    1024
#define W_LO_OFF 65536
#define SM_S0   (1024 + 131072)
#define SM_S1   (SM_S0 + 32768)
#define SM_S2   (SM_S1 + 32768)
#define SMEM_ALL (SM_S2 + 32768)    // 230400 B

// ---------------- grid barrier (all 128 CTAs resident, 1/SM) ----------------
__device__ __forceinline__ void grid_barrier(unsigned b) {
    __syncthreads();
    if (threadIdx.x == 0) {
        __threadfence();
        unsigned arrived = atomicAdd(&g_bar_count, 1u);
        if (arrived == NCTA - 1) {
            g_bar_count = 0;
            asm volatile("st.release.gpu.global.u32 [%0], %1;"
                         :: "l"(&g_bar_sense), "r"(b) : "memory");
        } else {
            unsigned s;
            do {
                asm volatile("ld.acquire.gpu.global.u32 %0, [%1];"
                             : "=r"(s) : "l"(&g_bar_sense) : "memory");
                if (s < b) __nanosleep(64);
            } while (s < b);
        }
    }
    __syncthreads();
}

// ---------------- prep ----------------
__global__ void prep_kernel(const float* __restrict__ W_in, const float* __restrict__ b_in,
                            const float* __restrict__ W_l, const float* __restrict__ b_l,
                            const float* __restrict__ W_r, const float* __restrict__ b_r) {
    int t = blockIdx.x * blockDim.x + threadIdx.x;
    int stride = gridDim.x * blockDim.x;
    if (t == 0) { g_bar_count = 0; g_bar_sense = 0; }
    for (int idx = t; idx < 256 * 128; idx += stride) {
        float w = (idx < 128 * 128) ? W_l[idx] : W_r[idx - 128 * 128];
        __nv_bfloat16 h = __float2bfloat16(w);
        g_WLhi[idx] = h;
        g_WLlo[idx] = __float2bfloat16(w - __bfloat162float(h));
    }
    for (int idx = t; idx < 64 * 128; idx += stride) {
        float w = W_in[idx];
        __nv_bfloat16 h = __float2bfloat16(w);
        g_WIhi[idx] = h;
        g_WIlo[idx] = __float2bfloat16(w - __bfloat162float(h));
    }
    if (t < 128) { g_bsum[t] = b_l[t] + b_r[t]; g_bin[t] = b_in[t]; }
}

// ---------------- persistent fused kernel ----------------
__global__ void __launch_bounds__(512, 1)
rnn_all(const float* __restrict__ leafX, float* __restrict__ out) {
    extern __shared__ char smem[];
    const uint32_t sb = (uint32_t)__cvta_generic_to_shared(smem);
    const int tid = threadIdx.x, l = tid & 31, wid = tid >> 5;
    const int wm = wid & 7, wn = wid >> 3;      // GEMM1: 8m x 2n, tile 128x128
    const int wm2 = wid & 3, wn2 = wid >> 2;    // GEMM2: 4m x 4n, tile 64x128
    const int cta = blockIdx.x;

    // ---- resident Wcat hi/lo ----
    for (int i = tid; i < 256 * 16; i += 512) {
        int kr = i >> 4, ch = i & 15;
        uint32_t off = SWZW((uint32_t)(kr * 256 + ch * 16));
        cp16(sb + SM_W + off, g_WLhi + (size_t)kr * 128 + ch * 8);
        cp16(sb + SM_W + W_LO_OFF + off, g_WLlo + (size_t)kr * 128 + ch * 8);
    }
    CP_COMMIT();
    if (tid < 128) {
        ((float*)(smem + SM_BIN))[tid]  = g_bin[tid];
        ((float*)(smem + SM_BSUM))[tid] = g_bsum[tid];
    }
    CP_WAIT(0);
    __syncthreads();

    // ---- GEMM1: one 64-wide K stage. A in slot `abase`, W at (wbase, wloff), k base st*64.
    auto compute_stage1 = [&](float (*acc)[4], uint32_t abase, uint32_t wbase,
                              uint32_t wloff, int st) {
        #pragma unroll
        for (int ks = 0; ks < 4; ks++) {
            uint32_t ah[4], al[4], bh[8][2], bl[8][2];
            {
                int row = wm * 16 + (l & 15);
                uint32_t aoff = SWZA((uint32_t)(row * 128 + ks * 32 + (l >> 4) * 16));
                ldm_x4(ah, abase + aoff);
                ldm_x4(al, abase + 16384 + aoff);
            }
            #pragma unroll
            for (int ntp = 0; ntp < 4; ntp++) {
                int krow = st * 64 + ks * 16 + (l & 15);
                int nb   = (wn * 64 + ntp * 16 + (l >> 4) * 8) * 2;
                uint32_t woff = SWZW((uint32_t)(krow * 256 + nb));
                uint32_t t4[4];
                ldm_x4_t(t4, wbase + woff);
                bh[ntp * 2][0] = t4[0]; bh[ntp * 2][1] = t4[1];
                bh[ntp * 2 + 1][0] = t4[2]; bh[ntp * 2 + 1][1] = t4[3];
                ldm_x4_t(t4, wbase + wloff + woff);
                bl[ntp * 2][0] = t4[0]; bl[ntp * 2][1] = t4[1];
                bl[ntp * 2 + 1][0] = t4[2]; bl[ntp * 2 + 1][1] = t4[3];
            }
            #pragma unroll
            for (int nt = 0; nt < 8; nt++) mma_bf16(acc[nt], ah, bh[nt]);
            #pragma unroll
            for (int nt = 0; nt < 8; nt++) mma_bf16(acc[nt], ah, bl[nt]);
            #pragma unroll
            for (int nt = 0; nt < 8; nt++) mma_bf16(acc[nt], al, bh[nt]);
        }
    };

    // ---- epilogue1: bias+tanh H(128 rows) -> smem P (64 rows x 512B, SWZB) in S1/S2.
    auto epilogue1 = [&](float (*acc)[4], const float* sBias) {
        #pragma unroll
        for (int nt = 0; nt < 8; nt++) {
            int c = wn * 64 + nt * 8 + (l & 3) * 2;
            #pragma unroll
            for (int half = 0; half < 2; half++) {
                int gm = wm * 16 + (l >> 2) + half * 8;
                float x0 = acc[nt][half * 2]     + sBias[c];
                float x1 = acc[nt][half * 2 + 1] + sBias[c + 1];
                float t0 = tanhf(x0), t1 = tanhf(x1);
                uint32_t hp = f2bf2(t0, t1);
                uint32_t lp = f2bf2(t0 - bf_lo(hp), t1 - bf_hi(hp));
                uint32_t off = SWZB((uint32_t)((gm >> 1) * 512 + ((gm & 1) * 128 + c) * 2));
                *(uint32_t*)(smem + SM_S1 + off) = hp;
                *(uint32_t*)(smem + SM_S2 + off) = lp;
            }
        }
    };

    // ---- GEMM2: 64 rows x 128, K=256. A = smem P (S1/S2, SWZB), W resident.
    auto compute_g2 = [&](float (*acc2)[4]) {
        #pragma unroll 4
        for (int ks2 = 0; ks2 < 16; ks2++) {
            uint32_t ah[4], al[4], bh[4][2], bl[4][2];
            {
                int row = wm2 * 16 + (l & 15);
                uint32_t aoff = SWZB((uint32_t)(row * 512 + ks2 * 32 + (l >> 4) * 16));
                ldm_x4(ah, sb + SM_S1 + aoff);
                ldm_x4(al, sb + SM_S2 + aoff);
            }
            #pragma unroll
            for (int ntp = 0; ntp < 2; ntp++) {
                int krow = ks2 * 16 + (l & 15);
                int nb   = (wn2 * 32 + ntp * 16 + (l >> 4) * 8) * 2;
                uint32_t woff = SWZW((uint32_t)(krow * 256 + nb));
                uint32_t t4[4];
                ldm_x4_t(t4, sb + SM_W + woff);
                bh[ntp * 2][0] = t4[0]; bh[ntp * 2][1] = t4[1];
                bh[ntp * 2 + 1][0] = t4[2]; bh[ntp * 2 + 1][1] = t4[3];
                ldm_x4_t(t4, sb + SM_W + W_LO_OFF + woff);
                bl[ntp * 2][0] = t4[0]; bl[ntp * 2][1] = t4[1];
                bl[ntp * 2 + 1][0] = t4[2]; bl[ntp * 2 + 1][1] = t4[3];
            }
            #pragma unroll
            for (int nt = 0; nt < 4; nt++) mma_bf16(acc2[nt], ah, bh[nt]);
            #pragma unroll
            for (int nt = 0; nt < 4; nt++) mma_bf16(acc2[nt], ah, bl[nt]);
            #pragma unroll
            for (int nt = 0; nt < 4; nt++) mma_bf16(acc2[nt], al, bh[nt]);
        }
    };

    // ---- epilogue2g: H(64 rows) -> global P pairs at row base rb.
    auto epilogue2g = [&](float (*acc2)[4], const float* sBias,
                          __nv_bfloat16* nHi, __nv_bfloat16* nLo, int rb) {
        #pragma unroll
        for (int nt = 0; nt < 4; nt++) {
            int c = wn2 * 32 + nt * 8 + (l & 3) * 2;
            #pragma unroll
            for (int half = 0; half < 2; half++) {
                int gm = wm2 * 16 + (l >> 2) + half * 8;
                float x0 = acc2[nt][half * 2]     + sBias[c];
                float x1 = acc2[nt][half * 2 + 1] + sBias[c + 1];
                float t0 = tanhf(x0), t1 = tanhf(x1);
                uint32_t hp = f2bf2(t0, t1);
                uint32_t lp = f2bf2(t0 - bf_lo(hp), t1 - bf_hi(hp));
                size_t base = (size_t)(rb + (gm >> 1)) * 256 + (size_t)((gm & 1) * 128 + c);
                *(uint32_t*)(nHi + base) = hp;
                *(uint32_t*)(nLo + base) = lp;
            }
        }
    };

    // ---- epilogue2s: H(64 rows) -> smem P (final phase); last level -> out.
    auto epilogue2s = [&](float (*acc2)[4], const float* sBias, bool lastlv) {
        #pragma unroll
        for (int nt = 0; nt < 4; nt++) {
            int c = wn2 * 32 + nt * 8 + (l & 3) * 2;
            #pragma unroll
            for (int half = 0; half < 2; half++) {
                int gm = wm2 * 16 + (l >> 2) + half * 8;
                float x0 = acc2[nt][half * 2]     + sBias[c];
                float x1 = acc2[nt][half * 2 + 1] + sBias[c + 1];
                float t0 = tanhf(x0), t1 = tanhf(x1);
                if (lastlv) {
                    if (gm == 0) { out[c] = t0; out[c + 1] = t1; }
                } else {
                    uint32_t hp = f2bf2(t0, t1);
                    uint32_t lp = f2bf2(t0 - bf_lo(hp), t1 - bf_hi(hp));
                    uint32_t off = SWZB((uint32_t)((gm >> 1) * 512 + ((gm & 1) * 128 + c) * 2));
                    *(uint32_t*)(smem + SM_S1 + off) = hp;
                    *(uint32_t*)(smem + SM_S2 + off) = lp;
                }
            }
        }
    };

    const float* sBin  = (const float*)(smem + SM_BIN);
    const float* sBsum = (const float*)(smem + SM_BSUM);

    // ============ PHASE L: leaf + level 1 fused ============
    for (int t = cta; t < NLV / 128; t += NCTA) {
        const int m0 = t * 128;
        // W_in hi/lo -> S1 (32KB slot: hi at 0, lo at +16K); L2-hot broadcast.
        for (int i = tid; i < 64 * 16; i += 512) {
            int kr = i >> 4, ch = i & 15;
            uint32_t off = SWZW((uint32_t)(kr * 256 + ch * 16));
            cp16(sb + SM_S1 + off, g_WIhi + (size_t)kr * 128 + ch * 8);
            cp16(sb + SM_S1 + 16384 + off, g_WIlo + (size_t)kr * 128 + ch * 8);
        }
        CP_COMMIT();
        // leafX fp32 -> bf16 hi/lo into S0
        for (int i = tid; i < 1024; i += 512) {
            int r = i >> 3, kg = i & 7;
            const float* src = leafX + (size_t)(m0 + r) * 64 + kg * 8;
            float4 f0 = *(const float4*)src;
            float4 f1 = *(const float4*)(src + 4);
            float xs[8] = {f0.x, f0.y, f0.z, f0.w, f1.x, f1.y, f1.z, f1.w};
            uint32_t hp[4], lp[4];
            #pragma unroll
            for (int j = 0; j < 4; j++) {
                hp[j] = f2bf2(xs[2 * j], xs[2 * j + 1]);
                lp[j] = f2bf2(xs[2 * j] - bf_lo(hp[j]), xs[2 * j + 1] - bf_hi(hp[j]));
            }
            uint32_t off = SWZA((uint32_t)(r * 128 + kg * 16));
            *(uint4*)(smem + SM_S0 + off)         = make_uint4(hp[0], hp[1], hp[2], hp[3]);
            *(uint4*)(smem + SM_S0 + 16384 + off) = make_uint4(lp[0], lp[1], lp[2], lp[3]);
        }
        CP_WAIT(0);
        __syncthreads();

        float acc[8][4];
        #pragma unroll
        for (int nt = 0; nt < 8; nt++)
            #pragma unroll
            for (int q = 0; q < 4; q++) acc[nt][q] = 0.f;
        compute_stage1(acc, sb + SM_S0, sb + SM_S1, 16384, 0);   // K=64
        __syncthreads();
        epilogue1(acc, sBin);                                     // H0 -> smem P0
        __syncthreads();

        float acc2[4][4];
        #pragma unroll
        for (int nt = 0; nt < 4; nt++)
            #pragma unroll
            for (int q = 0; q < 4; q++) acc2[nt][q] = 0.f;
        compute_g2(acc2);                                         // level 1
        __syncthreads();
        epilogue2g(acc2, sBsum, g_Ahi, g_Alo, t * 32);            // P1 rows
    }
    unsigned bar = 1;
    grid_barrier(bar);

    // ============ PHASE D: 5 fused double-levels (levels 2..11) ============
    const __nv_bfloat16* cH = g_Ahi;
    const __nv_bfloat16* cL = g_Alo;
    int R = 65536;    // P1 rows
    for (int d = 0; d < 5; d++) {
        __nv_bfloat16* nH = (cH == g_Ahi) ? g_Bhi : g_Ahi;
        __nv_bfloat16* nL = (cL == g_Alo) ? g_Blo : g_Alo;
        const int tiles = R >> 7;

        auto load_a = [&](int m0, int st, uint32_t slot) {
            #pragma unroll 2
            for (int i = tid; i < 1024; i += 512) {
                int r = i >> 3, kg = i & 7;
                uint32_t off = SWZA((uint32_t)(r * 128 + kg * 16));
                size_t gi = (size_t)(m0 + r) * 256 + st * 64 + kg * 8;
                cp16(slot + off, cH + gi);
                cp16(slot + 16384 + off, cL + gi);
            }
        };

        for (int t = cta; t < tiles; t += NCTA) {
            const int m0 = t * 128;
            float acc[8][4];
            #pragma unroll
            for (int nt = 0; nt < 8; nt++)
                #pragma unroll
                for (int q = 0; q < 4; q++) acc[nt][q] = 0.f;

            load_a(m0, 0, sb + SM_S0); CP_COMMIT();
            load_a(m0, 1, sb + SM_S1); CP_COMMIT();
            load_a(m0, 2, sb + SM_S2); CP_COMMIT();
            CP_WAIT(2); __syncthreads();
            compute_stage1(acc, sb + SM_S0, sb + SM_W, W_LO_OFF, 0);
            __syncthreads();
            load_a(m0, 3, sb + SM_S0); CP_COMMIT();
            CP_WAIT(2); __syncthreads();
            compute_stage1(acc, sb + SM_S1, sb + SM_W, W_LO_OFF, 1);
            __syncthreads();
            CP_WAIT(1); __syncthreads();
            compute_stage1(acc, sb + SM_S2, sb + SM_W, W_LO_OFF, 2);
            __syncthreads();
            CP_WAIT(0); __syncthreads();
            compute_stage1(acc, sb + SM_S0, sb + SM_W, W_LO_OFF, 3);
            __syncthreads();

            epilogue1(acc, sBsum);            // H_L -> smem P (S1/S2)
            __syncthreads();

            float acc2[4][4];
            #pragma unroll
            for (int nt = 0; nt < 4; nt++)
                #pragma unroll
                for (int q = 0; q < 4; q++) acc2[nt][q] = 0.f;
            compute_g2(acc2);                 // level L+1
            __syncthreads();
            epilogue2g(acc2, sBsum, nH, nL, t * 32);
        }
        grid_barrier(++bar);
        cH = nH; cL = nL; R >>= 2;
    }

    // ============ PHASE F: last 7 levels (R=64 -> root), single CTA ============
    if (cta == 0) {
        // load P (64 rows) into S1/S2 (SWZB)
        for (int i = tid; i < 64 * 32; i += 512) {
            int r = i >> 5, ch = i & 31;
            uint32_t off = SWZB((uint32_t)(r * 512 + ch * 16));
            cp16(sb + SM_S1 + off, cH + (size_t)r * 256 + ch * 8);
            cp16(sb + SM_S2 + off, cL + (size_t)r * 256 + ch * 8);
        }
        CP_COMMIT(); CP_WAIT(0);
        __syncthreads();
        for (int lv = 0; lv < 7; lv++) {
            float acc2[4][4];
            #pragma unroll
            for (int nt = 0; nt < 4; nt++)
                #pragma unroll
                for (int q = 0; q < 4; q++) acc2[nt][q] = 0.f;
            compute_g2(acc2);
            __syncthreads();
            epilogue2s(acc2, sBsum, lv == 6);
            __syncthreads();
        }
    }
}

// ---------------- host ----------------
extern "C" void kernel_launch(void* const* d_in, const int* in_sizes, int n_in,
                              void* d_out, int out_size) {
    const float* leaf_x = (const float*)d_in[0];
    const float* W_in   = (const float*)d_in[1];
    const float* b_in   = (const float*)d_in[2];
    const float* W_l    = (const float*)d_in[3];
    const float* b_l    = (const float*)d_in[4];
    const float* W_r    = (const float*)d_in[5];
    const float* b_r    = (const float*)d_in[6];

    cudaFuncSetAttribute(rnn_all, cudaFuncAttributeMaxDynamicSharedMemorySize, SMEM_ALL);

    prep_kernel<<<64, 256>>>(W_in, b_in, W_l, b_l, W_r, b_r);
    rnn_all<<<NCTA, 512, SMEM_ALL>>>(leaf_x, (float*)d_out);
}

// round 15
// speedup vs baseline: 4.6759x; 1.0832x over previous
#include <cuda_runtime.h>
#include <cuda_bf16.h>
#include <math.h>
#include <stdint.h>

#define HID 128
#define NLV 262144
#define NCTA 128

// ---------------- device buffers (static = allocation-guard safe) ----------------
__device__ __nv_bfloat16 g_Ahi[(size_t)65536 * 256];    // 32 MB (P ping)
__device__ __nv_bfloat16 g_Alo[(size_t)65536 * 256];    // 32 MB
__device__ __nv_bfloat16 g_Bhi[(size_t)16384 * 256];    //  8 MB (P pong)
__device__ __nv_bfloat16 g_Blo[(size_t)16384 * 256];    //  8 MB
__device__ __nv_bfloat16 g_WLhi[256 * 128], g_WLlo[256 * 128];  // vstack(W_l,W_r)
__device__ __nv_bfloat16 g_WIhi[64 * 128],  g_WIlo[64 * 128];   // W_in
__device__ float g_bsum[128];
__device__ float g_bin[128];
__device__ unsigned g_bar_count;
__device__ unsigned g_bar_sense;

// ---------------- helpers ----------------
__device__ __forceinline__ uint32_t f2bf2(float a, float b) {
    uint32_t r;
    asm("cvt.rn.bf16x2.f32 %0, %1, %2;" : "=r"(r) : "f"(b), "f"(a));
    return r;
}
__device__ __forceinline__ float bf_lo(uint32_t p) { return __uint_as_float(p << 16); }
__device__ __forceinline__ float bf_hi(uint32_t p) { return __uint_as_float(p & 0xFFFF0000u); }

// Exact-formula fast tanh: (e^{2x}-1)/(e^{2x}+1) = 1 - 2/(e^{2x}+1).
// __expf/__fdividef: ~5 instr, abs err ~1e-7; inf/NaN-safe (exp->inf => 1, exp->0 => -1).
__device__ __forceinline__ float fast_tanh(float x) {
    float e = __expf(2.0f * x);
    return 1.0f - __fdividef(2.0f, e + 1.0f);
}

__device__ __forceinline__ void ldm_x4(uint32_t* r, uint32_t addr) {
    asm volatile("ldmatrix.sync.aligned.m8n8.x4.shared.b16 {%0,%1,%2,%3}, [%4];"
                 : "=r"(r[0]), "=r"(r[1]), "=r"(r[2]), "=r"(r[3]) : "r"(addr));
}
__device__ __forceinline__ void ldm_x4_t(uint32_t* r, uint32_t addr) {
    asm volatile("ldmatrix.sync.aligned.m8n8.x4.trans.shared.b16 {%0,%1,%2,%3}, [%4];"
                 : "=r"(r[0]), "=r"(r[1]), "=r"(r[2]), "=r"(r[3]) : "r"(addr));
}
__device__ __forceinline__ void mma_bf16(float* c, const uint32_t* a, const uint32_t* b) {
    asm volatile("mma.sync.aligned.m16n8k16.row.col.f32.bf16.bf16.f32 "
                 "{%0,%1,%2,%3}, {%4,%5,%6,%7}, {%8,%9}, {%0,%1,%2,%3};"
                 : "+f"(c[0]), "+f"(c[1]), "+f"(c[2]), "+f"(c[3])
                 : "r"(a[0]), "r"(a[1]), "r"(a[2]), "r"(a[3]), "r"(b[0]), "r"(b[1]));
}
__device__ __forceinline__ void cp16(uint32_t dst, const void* src) {
    asm volatile("cp.async.ca.shared.global [%0], [%1], 16;" :: "r"(dst), "l"(src));
}
#define CP_COMMIT() asm volatile("cp.async.commit_group;" ::: "memory")
#define CP_WAIT(N)  asm volatile("cp.async.wait_group %0;" :: "n"(N) : "memory")

// SWZA: A tiles, 128B rows. SWZW: W, 256B rows. SWZB: smem P, 512B rows.
#define SWZA(o) ((o) ^ ((((uint32_t)(o)) >> 3) & 0x70))
#define SWZW(o) ((o) ^ (((((uint32_t)(o)) >> 8) & 7) << 4))
#define SWZB(o) ((o) ^ (((((uint32_t)(o)) >> 9) & 7) << 4))

// ---------------- smem layout ----------------
#define SM_BIN  0
#define SM_BSUM 512
#define SM_W    1024
#define W_LO_OFF 65536
#define SM_S0   (1024 + 131072)
#define SM_S1   (SM_S0 + 32768)
#define SM_S2   (SM_S1 + 32768)
#define SMEM_ALL (SM_S2 + 32768)    // 230400 B

// ---------------- grid barrier (all 128 CTAs resident, 1/SM) ----------------
__device__ __forceinline__ void grid_barrier(unsigned b) {
    __syncthreads();
    if (threadIdx.x == 0) {
        __threadfence();
        unsigned arrived = atomicAdd(&g_bar_count, 1u);
        if (arrived == NCTA - 1) {
            g_bar_count = 0;
            asm volatile("st.release.gpu.global.u32 [%0], %1;"
                         :: "l"(&g_bar_sense), "r"(b) : "memory");
        } else {
            unsigned s;
            do {
                asm volatile("ld.acquire.gpu.global.u32 %0, [%1];"
                             : "=r"(s) : "l"(&g_bar_sense) : "memory");
                if (s < b) __nanosleep(64);
            } while (s < b);
        }
    }
    __syncthreads();
}

// ---------------- prep ----------------
__global__ void prep_kernel(const float* __restrict__ W_in, const float* __restrict__ b_in,
                            const float* __restrict__ W_l, const float* __restrict__ b_l,
                            const float* __restrict__ W_r, const float* __restrict__ b_r) {
    int t = blockIdx.x * blockDim.x + threadIdx.x;
    int stride = gridDim.x * blockDim.x;
    if (t == 0) { g_bar_count = 0; g_bar_sense = 0; }
    for (int idx = t; idx < 256 * 128; idx += stride) {
        float w = (idx < 128 * 128) ? W_l[idx] : W_r[idx - 128 * 128];
        __nv_bfloat16 h = __float2bfloat16(w);
        g_WLhi[idx] = h;
        g_WLlo[idx] = __float2bfloat16(w - __bfloat162float(h));
    }
    for (int idx = t; idx < 64 * 128; idx += stride) {
        float w = W_in[idx];
        __nv_bfloat16 h = __float2bfloat16(w);
        g_WIhi[idx] = h;
        g_WIlo[idx] = __float2bfloat16(w - __bfloat162float(h));
    }
    if (t < 128) { g_bsum[t] = b_l[t] + b_r[t]; g_bin[t] = b_in[t]; }
}

// ---------------- persistent fused kernel ----------------
__global__ void __launch_bounds__(512, 1)
rnn_all(const float* __restrict__ leafX, float* __restrict__ out) {
    extern __shared__ char smem[];
    const uint32_t sb = (uint32_t)__cvta_generic_to_shared(smem);
    const int tid = threadIdx.x, l = tid & 31, wid = tid >> 5;
    const int wm = wid & 7, wn = wid >> 3;      // GEMM1: 8m x 2n, tile 128x128
    const int wm2 = wid >> 2, wn2 = wid & 3;    // GEMM2: 4m x 4n (m varies slow ->
                                                // small-Mo active warps spread over SMSPs)
    const int cta = blockIdx.x;

    // ---- resident Wcat hi/lo ----
    for (int i = tid; i < 256 * 16; i += 512) {
        int kr = i >> 4, ch = i & 15;
        uint32_t off = SWZW((uint32_t)(kr * 256 + ch * 16));
        cp16(sb + SM_W + off, g_WLhi + (size_t)kr * 128 + ch * 8);
        cp16(sb + SM_W + W_LO_OFF + off, g_WLlo + (size_t)kr * 128 + ch * 8);
    }
    CP_COMMIT();
    if (tid < 128) {
        ((float*)(smem + SM_BIN))[tid]  = g_bin[tid];
        ((float*)(smem + SM_BSUM))[tid] = g_bsum[tid];
    }
    CP_WAIT(0);
    __syncthreads();

    // ---- GEMM1: one 64-wide K stage ----
    auto compute_stage1 = [&](float (*acc)[4], uint32_t abase, uint32_t wbase,
                              uint32_t wloff, int st) {
        #pragma unroll
        for (int ks = 0; ks < 4; ks++) {
            uint32_t ah[4], al[4], bh[8][2], bl[8][2];
            {
                int row = wm * 16 + (l & 15);
                uint32_t aoff = SWZA((uint32_t)(row * 128 + ks * 32 + (l >> 4) * 16));
                ldm_x4(ah, abase + aoff);
                ldm_x4(al, abase + 16384 + aoff);
            }
            #pragma unroll
            for (int ntp = 0; ntp < 4; ntp++) {
                int krow = st * 64 + ks * 16 + (l & 15);
                int nb   = (wn * 64 + ntp * 16 + (l >> 4) * 8) * 2;
                uint32_t woff = SWZW((uint32_t)(krow * 256 + nb));
                uint32_t t4[4];
                ldm_x4_t(t4, wbase + woff);
                bh[ntp * 2][0] = t4[0]; bh[ntp * 2][1] = t4[1];
                bh[ntp * 2 + 1][0] = t4[2]; bh[ntp * 2 + 1][1] = t4[3];
                ldm_x4_t(t4, wbase + wloff + woff);
                bl[ntp * 2][0] = t4[0]; bl[ntp * 2][1] = t4[1];
                bl[ntp * 2 + 1][0] = t4[2]; bl[ntp * 2 + 1][1] = t4[3];
            }
            #pragma unroll
            for (int nt = 0; nt < 8; nt++) mma_bf16(acc[nt], ah, bh[nt]);
            #pragma unroll
            for (int nt = 0; nt < 8; nt++) mma_bf16(acc[nt], ah, bl[nt]);
            #pragma unroll
            for (int nt = 0; nt < 8; nt++) mma_bf16(acc[nt], al, bh[nt]);
        }
    };

    // ---- epilogue1: bias+tanh H(128 rows) -> smem P (64 rows x 512B, SWZB) in S1/S2.
    auto epilogue1 = [&](float (*acc)[4], const float* sBias) {
        #pragma unroll
        for (int nt = 0; nt < 8; nt++) {
            int c = wn * 64 + nt * 8 + (l & 3) * 2;
            #pragma unroll
            for (int half = 0; half < 2; half++) {
                int gm = wm * 16 + (l >> 2) + half * 8;
                float x0 = acc[nt][half * 2]     + sBias[c];
                float x1 = acc[nt][half * 2 + 1] + sBias[c + 1];
                float t0 = fast_tanh(x0), t1 = fast_tanh(x1);
                uint32_t hp = f2bf2(t0, t1);
                uint32_t lp = f2bf2(t0 - bf_lo(hp), t1 - bf_hi(hp));
                uint32_t off = SWZB((uint32_t)((gm >> 1) * 512 + ((gm & 1) * 128 + c) * 2));
                *(uint32_t*)(smem + SM_S1 + off) = hp;
                *(uint32_t*)(smem + SM_S2 + off) = lp;
            }
        }
    };

    // ---- GEMM2: up to 64 rows x 128, K=256. A = smem P, W resident.
    // mrows guard: warps whose m-tile is entirely garbage skip (spread over SMSPs).
    auto compute_g2 = [&](float (*acc2)[4], int mrows) {
        if (wm2 * 16 >= mrows) return;
        #pragma unroll 4
        for (int ks2 = 0; ks2 < 16; ks2++) {
            uint32_t ah[4], al[4], bh[4][2], bl[4][2];
            {
                int row = wm2 * 16 + (l & 15);
                uint32_t aoff = SWZB((uint32_t)(row * 512 + ks2 * 32 + (l >> 4) * 16));
                ldm_x4(ah, sb + SM_S1 + aoff);
                ldm_x4(al, sb + SM_S2 + aoff);
            }
            #pragma unroll
            for (int ntp = 0; ntp < 2; ntp++) {
                int krow = ks2 * 16 + (l & 15);
                int nb   = (wn2 * 32 + ntp * 16 + (l >> 4) * 8) * 2;
                uint32_t woff = SWZW((uint32_t)(krow * 256 + nb));
                uint32_t t4[4];
                ldm_x4_t(t4, sb + SM_W + woff);
                bh[ntp * 2][0] = t4[0]; bh[ntp * 2][1] = t4[1];
                bh[ntp * 2 + 1][0] = t4[2]; bh[ntp * 2 + 1][1] = t4[3];
                ldm_x4_t(t4, sb + SM_W + W_LO_OFF + woff);
                bl[ntp * 2][0] = t4[0]; bl[ntp * 2][1] = t4[1];
                bl[ntp * 2 + 1][0] = t4[2]; bl[ntp * 2 + 1][1] = t4[3];
            }
            #pragma unroll
            for (int nt = 0; nt < 4; nt++) mma_bf16(acc2[nt], ah, bh[nt]);
            #pragma unroll
            for (int nt = 0; nt < 4; nt++) mma_bf16(acc2[nt], ah, bl[nt]);
            #pragma unroll
            for (int nt = 0; nt < 4; nt++) mma_bf16(acc2[nt], al, bh[nt]);
        }
    };

    // ---- epilogue2g: H(64 rows) -> global P pairs at row base rb.
    auto epilogue2g = [&](float (*acc2)[4], const float* sBias,
                          __nv_bfloat16* nHi, __nv_bfloat16* nLo, int rb) {
        #pragma unroll
        for (int nt = 0; nt < 4; nt++) {
            int c = wn2 * 32 + nt * 8 + (l & 3) * 2;
            #pragma unroll
            for (int half = 0; half < 2; half++) {
                int gm = wm2 * 16 + (l >> 2) + half * 8;
                float x0 = acc2[nt][half * 2]     + sBias[c];
                float x1 = acc2[nt][half * 2 + 1] + sBias[c + 1];
                float t0 = fast_tanh(x0), t1 = fast_tanh(x1);
                uint32_t hp = f2bf2(t0, t1);
                uint32_t lp = f2bf2(t0 - bf_lo(hp), t1 - bf_hi(hp));
                size_t base = (size_t)(rb + (gm >> 1)) * 256 + (size_t)((gm & 1) * 128 + c);
                *(uint32_t*)(nHi + base) = hp;
                *(uint32_t*)(nLo + base) = lp;
            }
        }
    };

    // ---- epilogue2s: H(<=64 rows) -> smem P (final phase); last level -> out.
    auto epilogue2s = [&](float (*acc2)[4], const float* sBias, bool lastlv, int mrows) {
        if (wm2 * 16 >= mrows) return;
        #pragma unroll
        for (int nt = 0; nt < 4; nt++) {
            int c = wn2 * 32 + nt * 8 + (l & 3) * 2;
            #pragma unroll
            for (int half = 0; half < 2; half++) {
                int gm = wm2 * 16 + (l >> 2) + half * 8;
                float x0 = acc2[nt][half * 2]     + sBias[c];
                float x1 = acc2[nt][half * 2 + 1] + sBias[c + 1];
                float t0 = fast_tanh(x0), t1 = fast_tanh(x1);
                if (lastlv) {
                    if (gm == 0) { out[c] = t0; out[c + 1] = t1; }
                } else {
                    uint32_t hp = f2bf2(t0, t1);
                    uint32_t lp = f2bf2(t0 - bf_lo(hp), t1 - bf_hi(hp));
                    uint32_t off = SWZB((uint32_t)((gm >> 1) * 512 + ((gm & 1) * 128 + c) * 2));
                    *(uint32_t*)(smem + SM_S1 + off) = hp;
                    *(uint32_t*)(smem + SM_S2 + off) = lp;
                }
            }
        }
    };

    const float* sBin  = (const float*)(smem + SM_BIN);
    const float* sBsum = (const float*)(smem + SM_BSUM);

    // ============ PHASE L: leaf + level 1 fused ============
    for (int t = cta; t < NLV / 128; t += NCTA) {
        const int m0 = t * 128;
        for (int i = tid; i < 64 * 16; i += 512) {
            int kr = i >> 4, ch = i & 15;
            uint32_t off = SWZW((uint32_t)(kr * 256 + ch * 16));
            cp16(sb + SM_S1 + off, g_WIhi + (size_t)kr * 128 + ch * 8);
            cp16(sb + SM_S1 + 16384 + off, g_WIlo + (size_t)kr * 128 + ch * 8);
        }
        CP_COMMIT();
        for (int i = tid; i < 1024; i += 512) {
            int r = i >> 3, kg = i & 7;
            const float* src = leafX + (size_t)(m0 + r) * 64 + kg * 8;
            float4 f0 = *(const float4*)src;
            float4 f1 = *(const float4*)(src + 4);
            float xs[8] = {f0.x, f0.y, f0.z, f0.w, f1.x, f1.y, f1.z, f1.w};
            uint32_t hp[4], lp[4];
            #pragma unroll
            for (int j = 0; j < 4; j++) {
                hp[j] = f2bf2(xs[2 * j], xs[2 * j + 1]);
                lp[j] = f2bf2(xs[2 * j] - bf_lo(hp[j]), xs[2 * j + 1] - bf_hi(hp[j]));
            }
            uint32_t off = SWZA((uint32_t)(r * 128 + kg * 16));
            *(uint4*)(smem + SM_S0 + off)         = make_uint4(hp[0], hp[1], hp[2], hp[3]);
            *(uint4*)(smem + SM_S0 + 16384 + off) = make_uint4(lp[0], lp[1], lp[2], lp[3]);
        }
        CP_WAIT(0);
        __syncthreads();

        float acc[8][4];
        #pragma unroll
        for (int nt = 0; nt < 8; nt++)
            #pragma unroll
            for (int q = 0; q < 4; q++) acc[nt][q] = 0.f;
        compute_stage1(acc, sb + SM_S0, sb + SM_S1, 16384, 0);
        __syncthreads();
        epilogue1(acc, sBin);
        __syncthreads();

        float acc2[4][4];
        #pragma unroll
        for (int nt = 0; nt < 4; nt++)
            #pragma unroll
            for (int q = 0; q < 4; q++) acc2[nt][q] = 0.f;
        compute_g2(acc2, 64);
        __syncthreads();
        epilogue2g(acc2, sBsum, g_Ahi, g_Alo, t * 32);
    }
    unsigned bar = 1;
    grid_barrier(bar);

    // ============ PHASE D: 5 fused double-levels ============
    const __nv_bfloat16* cH = g_Ahi;
    const __nv_bfloat16* cL = g_Alo;
    int R = 65536;
    for (int d = 0; d < 5; d++) {
        __nv_bfloat16* nH = (cH == g_Ahi) ? g_Bhi : g_Ahi;
        __nv_bfloat16* nL = (cL == g_Alo) ? g_Blo : g_Alo;
        const int tiles = R >> 7;

        auto load_a = [&](int m0, int st, uint32_t slot) {
            #pragma unroll 2
            for (int i = tid; i < 1024; i += 512) {
                int r = i >> 3, kg = i & 7;
                uint32_t off = SWZA((uint32_t)(r * 128 + kg * 16));
                size_t gi = (size_t)(m0 + r) * 256 + st * 64 + kg * 8;
                cp16(slot + off, cH + gi);
                cp16(slot + 16384 + off, cL + gi);
            }
        };

        bool first = true;
        for (int t = cta; t < tiles; t += NCTA) {
            const int m0 = t * 128;
            if (first) { load_a(m0, 0, sb + SM_S0); CP_COMMIT(); first = false; }
            load_a(m0, 1, sb + SM_S1); CP_COMMIT();
            load_a(m0, 2, sb + SM_S2); CP_COMMIT();

            float acc[8][4];
            #pragma unroll
            for (int nt = 0; nt < 8; nt++)
                #pragma unroll
                for (int q = 0; q < 4; q++) acc[nt][q] = 0.f;

            CP_WAIT(2); __syncthreads();
            compute_stage1(acc, sb + SM_S0, sb + SM_W, W_LO_OFF, 0);
            __syncthreads();
            load_a(m0, 3, sb + SM_S0); CP_COMMIT();
            CP_WAIT(2); __syncthreads();
            compute_stage1(acc, sb + SM_S1, sb + SM_W, W_LO_OFF, 1);
            __syncthreads();
            CP_WAIT(1); __syncthreads();
            compute_stage1(acc, sb + SM_S2, sb + SM_W, W_LO_OFF, 2);
            __syncthreads();
            CP_WAIT(0); __syncthreads();
            compute_stage1(acc, sb + SM_S0, sb + SM_W, W_LO_OFF, 3);
            __syncthreads();

            epilogue1(acc, sBsum);
            __syncthreads();

            // prefetch next tile's stage 0 into S0 while GEMM2 runs on S1/S2
            int tn = t + NCTA;
            if (tn < tiles) { load_a(tn * 128, 0, sb + SM_S0); CP_COMMIT(); }

            float acc2[4][4];
            #pragma unroll
            for (int nt = 0; nt < 4; nt++)
                #pragma unroll
                for (int q = 0; q < 4; q++) acc2[nt][q] = 0.f;
            compute_g2(acc2, 64);
            __syncthreads();
            epilogue2g(acc2, sBsum, nH, nL, t * 32);
        }
        grid_barrier(++bar);
        cH = nH; cL = nL; R >>= 2;
    }

    // ============ PHASE F: last 7 levels (64 -> root), single CTA ============
    if (cta == 0) {
        for (int i = tid; i < 64 * 32; i += 512) {
            int r = i >> 5, ch = i & 31;
            uint32_t off = SWZB((uint32_t)(r * 512 + ch * 16));
            cp16(sb + SM_S1 + off, cH + (size_t)r * 256 + ch * 8);
            cp16(sb + SM_S2 + off, cL + (size_t)r * 256 + ch * 8);
        }
        CP_COMMIT(); CP_WAIT(0);
        __syncthreads();
        int Mo = 64;
        for (int lv = 0; lv < 7; lv++) {
            float acc2[4][4];
            #pragma unroll
            for (int nt = 0; nt < 4; nt++)
                #pragma unroll
                for (int q = 0; q < 4; q++) acc2[nt][q] = 0.f;
            compute_g2(acc2, Mo);
            __syncthreads();
            epilogue2s(acc2, sBsum, lv == 6, Mo);
            __syncthreads();
            Mo >>= 1;
        }
    }
}

// ---------------- host ----------------
extern "C" void kernel_launch(void* const* d_in, const int* in_sizes, int n_in,
                              void* d_out, int out_size) {
    const float* leaf_x = (const float*)d_in[0];
    const float* W_in   = (const float*)d_in[1];
    const float* b_in   = (const float*)d_in[2];
    const float* W_l    = (const float*)d_in[3];
    const float* b_l    = (const float*)d_in[4];
    const float* W_r    = (const float*)d_in[5];
    const float* b_r    = (const float*)d_in[6];

    cudaFuncSetAttribute(rnn_all, cudaFuncAttributeMaxDynamicSharedMemorySize, SMEM_ALL);

    prep_kernel<<<64, 256>>>(W_in, b_in, W_l, b_l, W_r, b_r);
    rnn_all<<<NCTA, 512, SMEM_ALL>>>(leaf_x, (float*)d_out);
}